// round 1
// baseline (speedup 1.0000x reference)
#include <cuda_runtime.h>
#include <math.h>

#define Bb 16
#define Hh 512
#define Ll 2048
#define Nn 64

typedef unsigned long long ull;

// ---------------- scratch (device globals; no allocations allowed) ----------
__device__ float2 d_A [Hh * Nn];   // per-(h,n) recurrence multiplier exp(dt*Lambda)
__device__ float2 d_Wk[Hh * Nn];   // per-(h,n) output weight (complex)
__device__ float  d_g [(size_t)Bb * Hh * Ll]; // gelu(conv + D*u), GEMM input

// ---------------- f32x2 packed-FMA helpers (Blackwell) ----------------------
__device__ __forceinline__ ull f2dup(float x) {
    ull r; asm("mov.b64 %0, {%1,%1};" : "=l"(r) : "f"(x)); return r;
}
__device__ __forceinline__ void fma2(ull& d, ull a, ull b, ull c) {
    asm("fma.rn.f32x2 %0, %1, %2, %3;" : "=l"(d) : "l"(a), "l"(b), "l"(c));
}
__device__ __forceinline__ float2 f2unpk(ull v) {
    float2 f; asm("mov.b64 {%0,%1}, %2;" : "=f"(f.x), "=f"(f.y) : "l"(v)); return f;
}

// ---------------- kernel 1: DSS coefficient prep ----------------------------
// dt_Lambda = exp(log_dt) (split re/im) * Lambda
// num = exp(dt_Lambda_neg)-1 ; den = exp(dt_Lambda_neg*L)-1
// Wk = W * num * conj(den*Lam)/(|den*Lam|^2 + EPS) ; A = exp(dt_Lambda)
__global__ void prep_kernel(const float* __restrict__ log_dt,
                            const float* __restrict__ Lambda,
                            const float* __restrict__ W) {
    int h = blockIdx.x;
    int n = threadIdx.x;
    float dt_re = expf(log_dt[2 * h + 0]);
    float dt_im = expf(log_dt[2 * h + 1]);
    float lr = Lambda[2 * n + 0], li = Lambda[2 * n + 1];
    float zr = dt_re * lr, zi = dt_im * li;      // dt_Lambda
    float sgn = (lr > 0.f) ? -1.f : 1.f;         // (1 - 2*pos); inputs give pos=0
    float nr = zr * sgn, ni = zi * sgn;          // dt_Lambda_neg
    float er = expf(nr);
    float num_re = er * cosf(ni) - 1.f;
    float num_im = er * sinf(ni);
    float eL = expf(nr * (float)Ll);
    float den_re = eL * cosf(ni * (float)Ll) - 1.f;
    float den_im = eL * sinf(ni * (float)Ll);
    float xr = den_re * lr - den_im * li;
    float xi = den_re * li + den_im * lr;
    float inv = 1.f / (xr * xr + xi * xi + 1e-7f);
    float rr = xr * inv, ri = -xi * inv;         // bounded reciprocal
    float wr = W[(h * Nn + n) * 2 + 0], wi = W[(h * Nn + n) * 2 + 1];
    float t1r = wr * num_re - wi * num_im;
    float t1i = wr * num_im + wi * num_re;
    d_Wk[h * Nn + n] = make_float2(t1r * rr - t1i * ri, t1r * ri + t1i * rr);
    float ea = expf(zr);
    d_A [h * Nn + n] = make_float2(ea * cosf(zi), ea * sinf(zi));
}

// ---------------- kernel 2: diagonal SSM scan + D skip + erf-GELU -----------
// One warp per (b,h). Each lane owns states n=lane and n=lane+32.
__global__ void scan_kernel(const float* __restrict__ u, const float* __restrict__ D) {
    int w    = blockIdx.x * (blockDim.x >> 5) + (threadIdx.x >> 5);
    int lane = threadIdx.x & 31;
    int b = w >> 9;          // / 512
    int h = w & (Hh - 1);
    const float* up = u   + (size_t)(b * Hh + h) * Ll;
    float*       gp = d_g + (size_t)(b * Hh + h) * Ll;
    float2 A0 = d_A [h * Nn + lane];
    float2 A1 = d_A [h * Nn + 32 + lane];
    float2 W0 = d_Wk[h * Nn + lane];
    float2 W1 = d_Wk[h * Nn + 32 + lane];
    float Dh = D[h];
    float s0r = 0.f, s0i = 0.f, s1r = 0.f, s1i = 0.f;

    for (int base = 0; base < Ll; base += 32) {
        float ur = up[base + lane];
        float ysave = 0.f;
#pragma unroll
        for (int s = 0; s < 32; s++) {
            float uv = __shfl_sync(0xffffffffu, ur, s);
            // s = A*s + u  (complex; u real)
            float p0  = A0.y * s0r;
            float n0i = fmaf(A0.x, s0i, p0);
            float n0r = fmaf(A0.x, s0r, uv);
            n0r = fmaf(-A0.y, s0i, n0r);
            s0r = n0r; s0i = n0i;
            float p1  = A1.y * s1r;
            float n1i = fmaf(A1.x, s1i, p1);
            float n1r = fmaf(A1.x, s1r, uv);
            n1r = fmaf(-A1.y, s1i, n1r);
            s1r = n1r; s1i = n1i;
            // c = Re(Wk0*s0 + Wk1*s1)
            float c = fmaf(s0r, W0.x, fmaf(-s0i, W0.y, fmaf(s1r, W1.x, -s1i * W1.y)));
            // butterfly reduce over the warp (sum over all 64 states)
            c += __shfl_xor_sync(0xffffffffu, c, 16);
            c += __shfl_xor_sync(0xffffffffu, c, 8);
            c += __shfl_xor_sync(0xffffffffu, c, 4);
            c += __shfl_xor_sync(0xffffffffu, c, 2);
            c += __shfl_xor_sync(0xffffffffu, c, 1);
            if (s == lane) ysave = c;   // lane keeps its own timestep
        }
        float y = fmaf(Dh, ur, ysave);                       // + D skip
        float g = 0.5f * y * (1.f + erff(y * 0.70710678118654752f)); // exact GELU
        gp[base + lane] = g;
    }
}

// ---------------- kernel 3: output mix out[b,v,l] = ow[v,:]@g[b,:,l] + bias --
#define BM 64
#define BN 128
#define BK 16
__global__ void gemm_kernel(const float* __restrict__ ow,
                            const float* __restrict__ bias,
                            float* __restrict__ out) {
    __shared__ __align__(16) float As[BK][BM];
    __shared__ __align__(16) float Bs[BK][BN];
    int b  = blockIdx.z;
    int v0 = blockIdx.y * BM;
    int l0 = blockIdx.x * BN;
    int t = threadIdx.x;
    int wid = t >> 5, lane = t & 31;
    const float* gbase = d_g + (size_t)b * Hh * Ll;

    ull acc[8][2];
#pragma unroll
    for (int i = 0; i < 8; i++) { acc[i][0] = 0ull; acc[i][1] = 0ull; }

    for (int k0 = 0; k0 < Hh; k0 += BK) {
        {   // A tile: ow[v0+v][k0+q*4 .. +3] -> As[k][v] (transposed)
            int v = t >> 2, q = t & 3;
            float4 a = *(const float4*)&ow[(size_t)(v0 + v) * Hh + k0 + q * 4];
            As[q * 4 + 0][v] = a.x;
            As[q * 4 + 1][v] = a.y;
            As[q * 4 + 2][v] = a.z;
            As[q * 4 + 3][v] = a.w;
        }
        {   // B tile: g[b][k0+r][l0+c..c+3]
            int r = t >> 5;
            int c = (t & 31) * 4;
            *(float4*)&Bs[r][c]     = *(const float4*)&gbase[(size_t)(k0 + r) * Ll + l0 + c];
            *(float4*)&Bs[r + 8][c] = *(const float4*)&gbase[(size_t)(k0 + r + 8) * Ll + l0 + c];
        }
        __syncthreads();
#pragma unroll
        for (int kk = 0; kk < BK; kk++) {
            ulonglong2 bb = *(const ulonglong2*)&Bs[kk][lane * 4];
            float4 a0 = *(const float4*)&As[kk][wid * 8];
            float4 a1 = *(const float4*)&As[kk][wid * 8 + 4];
            float av[8] = {a0.x, a0.y, a0.z, a0.w, a1.x, a1.y, a1.z, a1.w};
#pragma unroll
            for (int i = 0; i < 8; i++) {
                ull ap = f2dup(av[i]);
                fma2(acc[i][0], ap, bb.x, acc[i][0]);
                fma2(acc[i][1], ap, bb.y, acc[i][1]);
            }
        }
        __syncthreads();
    }
#pragma unroll
    for (int i = 0; i < 8; i++) {
        int v = v0 + wid * 8 + i;
        float bv = bias[v];
        float2 c0 = f2unpk(acc[i][0]);
        float2 c1 = f2unpk(acc[i][1]);
        float4 o = make_float4(c0.x + bv, c0.y + bv, c1.x + bv, c1.y + bv);
        *(float4*)&out[(size_t)(b * Hh + v) * Ll + l0 + lane * 4] = o;
    }
}

// ---------------- launch --------------------------------------------------
extern "C" void kernel_launch(void* const* d_in, const int* in_sizes, int n_in,
                              void* d_out, int out_size) {
    const float* u          = (const float*)d_in[0]; // (16,512,2048)
    const float* log_dt     = (const float*)d_in[1]; // (512,2)
    const float* Lambda     = (const float*)d_in[2]; // (64,2)
    const float* W          = (const float*)d_in[3]; // (1,512,64,2)
    const float* D          = (const float*)d_in[4]; // (1,512)
    const float* out_weight = (const float*)d_in[5]; // (512,512)
    const float* out_bias   = (const float*)d_in[6]; // (512,1)
    float* out = (float*)d_out;                      // (16,512,2048)

    prep_kernel<<<Hh, Nn>>>(log_dt, Lambda, W);
    scan_kernel<<<(Bb * Hh) / 8, 256>>>(u, D);
    dim3 grid(Ll / BN, Hh / BM, Bb);
    gemm_kernel<<<grid, 256>>>(out_weight, out_bias, out);
}

// round 3
// speedup vs baseline: 1.0981x; 1.0981x over previous
#include <cuda_runtime.h>
#include <cuda_bf16.h>
#include <math.h>

#define Bb 16
#define Hh 512
#define Ll 2048
#define Nn 64

typedef unsigned long long ull;
typedef unsigned short u16;
typedef unsigned int u32;

// ---------------- scratch (device globals; no allocations allowed) ----------
__device__ float2 d_A [Hh * Nn];
__device__ float2 d_Wk[Hh * Nn];
// g transposed: [b][l][u], bf16 hi / lo parts
__device__ __align__(16) u16 d_gh[(size_t)Bb * Ll * Hh];
__device__ __align__(16) u16 d_gl[(size_t)Bb * Ll * Hh];
// out_weight bf16 hi / lo: [v][u]
__device__ __align__(16) u16 d_owh[Hh * Hh];
__device__ __align__(16) u16 d_owl[Hh * Hh];

// ---------------- PTX helpers ----------------------------------------------
__device__ __forceinline__ u32 smem_u32(const void* p) {
    u32 a; asm("{ .reg .u64 t; cvta.to.shared.u64 t, %1; cvt.u32.u64 %0, t; }" : "=r"(a) : "l"(p));
    return a;
}
#define CP_ASYNC16(dst, src) asm volatile("cp.async.cg.shared.global [%0], [%1], 16;" :: "r"(dst), "l"(src) : "memory")
#define CP_COMMIT() asm volatile("cp.async.commit_group;" ::: "memory")
#define CP_WAIT(n)  asm volatile("cp.async.wait_group %0;" :: "n"(n) : "memory")

#define MMA16816(d, a, b) \
    asm volatile("mma.sync.aligned.m16n8k16.row.col.f32.bf16.bf16.f32 " \
        "{%0,%1,%2,%3}, {%4,%5,%6,%7}, {%8,%9}, {%0,%1,%2,%3};" \
        : "+f"((d)[0]), "+f"((d)[1]), "+f"((d)[2]), "+f"((d)[3]) \
        : "r"((a)[0]), "r"((a)[1]), "r"((a)[2]), "r"((a)[3]), "r"((b)[0]), "r"((b)[1]))

// ---------------- kernel 1a: DSS coefficient prep ---------------------------
__global__ void prep_kernel(const float* __restrict__ log_dt,
                            const float* __restrict__ Lambda,
                            const float* __restrict__ W) {
    int h = blockIdx.x;
    int n = threadIdx.x;
    float dt_re = expf(log_dt[2 * h + 0]);
    float dt_im = expf(log_dt[2 * h + 1]);
    float lr = Lambda[2 * n + 0], li = Lambda[2 * n + 1];
    float zr = dt_re * lr, zi = dt_im * li;
    float sgn = (lr > 0.f) ? -1.f : 1.f;
    float nr = zr * sgn, ni = zi * sgn;
    float er = expf(nr);
    float num_re = er * cosf(ni) - 1.f;
    float num_im = er * sinf(ni);
    float eL = expf(nr * (float)Ll);
    float den_re = eL * cosf(ni * (float)Ll) - 1.f;
    float den_im = eL * sinf(ni * (float)Ll);
    float xr = den_re * lr - den_im * li;
    float xi = den_re * li + den_im * lr;
    float inv = 1.f / (xr * xr + xi * xi + 1e-7f);
    float rr = xr * inv, ri = -xi * inv;
    float wr = W[(h * Nn + n) * 2 + 0], wi = W[(h * Nn + n) * 2 + 1];
    float t1r = wr * num_re - wi * num_im;
    float t1i = wr * num_im + wi * num_re;
    d_Wk[h * Nn + n] = make_float2(t1r * rr - t1i * ri, t1r * ri + t1i * rr);
    float ea = expf(zr);
    d_A [h * Nn + n] = make_float2(ea * cosf(zi), ea * sinf(zi));
}

// ---------------- kernel 1b: split out_weight into bf16 hi/lo ---------------
__global__ void owsplit_kernel(const float* __restrict__ ow) {
    int i = blockIdx.x * 256 + threadIdx.x;
    float x = ow[i];
    __nv_bfloat16 hi = __float2bfloat16(x);
    __nv_bfloat16 lo = __float2bfloat16(x - __bfloat162float(hi));
    d_owh[i] = __bfloat16_as_ushort(hi);
    d_owl[i] = __bfloat16_as_ushort(lo);
}

// ---------------- kernel 2: SSM scan + D skip + GELU, writes gT bf16 hi/lo --
__global__ void scan_kernel(const float* __restrict__ u, const float* __restrict__ D) {
    int b    = blockIdx.x >> 6;
    int hg   = blockIdx.x & 63;
    int t    = threadIdx.x;
    int w    = t >> 5;
    int lane = t & 31;
    int h    = hg * 8 + w;
    const float* up = u + (size_t)(b * Hh + h) * Ll;
    float2 A0 = d_A [h * Nn + lane];
    float2 A1 = d_A [h * Nn + 32 + lane];
    float2 W0 = d_Wk[h * Nn + lane];
    float2 W1 = d_Wk[h * Nn + 32 + lane];
    float Dh = D[h];
    float s0r = 0.f, s0i = 0.f, s1r = 0.f, s1i = 0.f;

    __shared__ u16 tH[32][10];
    __shared__ u16 tL[32][10];

    for (int base = 0; base < Ll; base += 32) {
        float ur = up[base + lane];
        float ysave = 0.f;
#pragma unroll
        for (int s = 0; s < 32; s++) {
            float uv = __shfl_sync(0xffffffffu, ur, s);
            float p0  = A0.y * s0r;
            float n0i = fmaf(A0.x, s0i, p0);
            float n0r = fmaf(A0.x, s0r, uv);
            n0r = fmaf(-A0.y, s0i, n0r);
            s0r = n0r; s0i = n0i;
            float p1  = A1.y * s1r;
            float n1i = fmaf(A1.x, s1i, p1);
            float n1r = fmaf(A1.x, s1r, uv);
            n1r = fmaf(-A1.y, s1i, n1r);
            s1r = n1r; s1i = n1i;
            float c = fmaf(s0r, W0.x, fmaf(-s0i, W0.y, fmaf(s1r, W1.x, -s1i * W1.y)));
            c += __shfl_xor_sync(0xffffffffu, c, 16);
            c += __shfl_xor_sync(0xffffffffu, c, 8);
            c += __shfl_xor_sync(0xffffffffu, c, 4);
            c += __shfl_xor_sync(0xffffffffu, c, 2);
            c += __shfl_xor_sync(0xffffffffu, c, 1);
            if (s == lane) ysave = c;
        }
        float y = fmaf(Dh, ur, ysave);
        float g = 0.5f * y * (1.f + erff(y * 0.70710678118654752f));
        __nv_bfloat16 hi = __float2bfloat16(g);
        __nv_bfloat16 lo = __float2bfloat16(g - __bfloat162float(hi));
        tH[lane][w] = __bfloat16_as_ushort(hi);
        tL[lane][w] = __bfloat16_as_ushort(lo);
        __syncthreads();
        if (t < 64) {
            int l = t >> 1, half = t & 1;
            int c0 = half * 4;
            u32 lo32h = (u32)tH[l][c0 + 0] | ((u32)tH[l][c0 + 1] << 16);
            u32 hi32h = (u32)tH[l][c0 + 2] | ((u32)tH[l][c0 + 3] << 16);
            u32 lo32l = (u32)tL[l][c0 + 0] | ((u32)tL[l][c0 + 1] << 16);
            u32 hi32l = (u32)tL[l][c0 + 2] | ((u32)tL[l][c0 + 3] << 16);
            size_t off = ((size_t)(b * Ll + base + l) * Hh) + hg * 8 + c0;
            *(uint2*)(d_gh + off) = make_uint2(lo32h, hi32h);
            *(uint2*)(d_gl + off) = make_uint2(lo32l, hi32l);
        }
        __syncthreads();
    }
}

// ---------------- kernel 3: HMMA (mma.sync) split-bf16 GEMM ------------------
// out[b,v,l] = sum_u ow[v,u] * g[b,l,u] + bias[v]
// CTA: 128(v) x 128(l), K-chunk 32, double-buffered cp.async.
#define BM 128
#define BN 128
#define BK 32
#define TSTRIDE 40                 // u16 elements per row (80 B, 16B-aligned, bank-staggered)
#define MATB (BM * TSTRIDE * 2)    // 10240 bytes per matrix part
#define BUFB (4 * MATB)            // AH, AL, BH, BL
#define GEMM_SMEM (2 * BUFB)       // 81920 bytes

__global__ void __launch_bounds__(256, 1)
gemm_hmma(const float* __restrict__ bias, float* __restrict__ out) {
    extern __shared__ __align__(16) char sm[];
    u16* S = (u16*)sm;             // [buf][part][row][TSTRIDE]
    const int t = threadIdx.x;
    const int wid = t >> 5, lane = t & 31;
    const int warp_m = wid & 3, warp_n = wid >> 2;
    const int qr = lane >> 2;          // 0..7
    const int qc = (lane & 3) * 2;     // 0,2,4,6
    const int b  = blockIdx.z;
    const int v0 = blockIdx.y * BM;
    const int l0 = blockIdx.x * BN;
    const size_t browbase = (size_t)(b * Ll + l0) * Hh;

    u32 sbase = smem_u32(S);

    float acc[2][8][4];
#pragma unroll
    for (int mt = 0; mt < 2; mt++)
#pragma unroll
        for (int nt = 0; nt < 8; nt++)
#pragma unroll
            for (int i = 0; i < 4; i++) acc[mt][nt][i] = 0.f;

    const int NK = Hh / BK;   // 16

    // ---- async tile loader: 512 16B segs per part-pair, 8 cp.async/thread --
    auto issue = [&](int c) {
        int k0 = c * BK;
        u32 dst = sbase + (c & 1) * BUFB;
#pragma unroll
        for (int j = 0; j < 2; j++) {
            int idx = t + 256 * j;
            int row = idx >> 2, seg = idx & 3;
            u32 so = (u32)(row * (TSTRIDE * 2) + seg * 16);
            size_t ga = (size_t)(v0 + row) * Hh + k0 + seg * 8;
            CP_ASYNC16(dst + so,            (const char*)(d_owh + ga));
            CP_ASYNC16(dst + MATB + so,     (const char*)(d_owl + ga));
            size_t gb = browbase + (size_t)row * Hh + k0 + seg * 8;
            CP_ASYNC16(dst + 2 * MATB + so, (const char*)(d_gh + gb));
            CP_ASYNC16(dst + 3 * MATB + so, (const char*)(d_gl + gb));
        }
        CP_COMMIT();
    };

    issue(0);
    for (int c = 0; c < NK; c++) {
        if (c + 1 < NK) { issue(c + 1); CP_WAIT(1); }
        else            { CP_WAIT(0); }
        __syncthreads();

        const u16* AH = S + (size_t)(c & 1) * (BUFB / 2);
        const u16* AL = AH + MATB / 2;
        const u16* BH = AH + MATB;
        const u16* BL = AH + 3 * (MATB / 2);

#pragma unroll
        for (int kk = 0; kk < BK; kk += 16) {
            u32 ah[2][4], al[2][4];
#pragma unroll
            for (int mt = 0; mt < 2; mt++) {
                int r0 = warp_m * 32 + mt * 16 + qr;
                int o00 = r0 * TSTRIDE + kk + qc;
                ah[mt][0] = *(const u32*)&AH[o00];
                ah[mt][1] = *(const u32*)&AH[o00 + 8 * TSTRIDE];
                ah[mt][2] = *(const u32*)&AH[o00 + 8];
                ah[mt][3] = *(const u32*)&AH[o00 + 8 * TSTRIDE + 8];
                al[mt][0] = *(const u32*)&AL[o00];
                al[mt][1] = *(const u32*)&AL[o00 + 8 * TSTRIDE];
                al[mt][2] = *(const u32*)&AL[o00 + 8];
                al[mt][3] = *(const u32*)&AL[o00 + 8 * TSTRIDE + 8];
            }
            u32 bh[8][2], bl[8][2];
#pragma unroll
            for (int nt = 0; nt < 8; nt++) {
                int n = warp_n * 64 + nt * 8 + qr;
                int o = n * TSTRIDE + kk + qc;
                bh[nt][0] = *(const u32*)&BH[o];
                bh[nt][1] = *(const u32*)&BH[o + 8];
                bl[nt][0] = *(const u32*)&BL[o];
                bl[nt][1] = *(const u32*)&BL[o + 8];
            }
#pragma unroll
            for (int mt = 0; mt < 2; mt++)
#pragma unroll
                for (int nt = 0; nt < 8; nt++) {
                    MMA16816(acc[mt][nt], ah[mt], bh[nt]);
                    MMA16816(acc[mt][nt], ah[mt], bl[nt]);
                    MMA16816(acc[mt][nt], al[mt], bh[nt]);
                }
        }
        __syncthreads();
    }

    // ---- epilogue ----------------------------------------------------------
#pragma unroll
    for (int mt = 0; mt < 2; mt++) {
        int vg = v0 + warp_m * 32 + mt * 16 + qr;
        float bv0 = bias[vg];
        float bv1 = bias[vg + 8];
        float* r0 = out + (size_t)(b * Hh + vg) * Ll + l0 + warp_n * 64;
        float* r1 = r0 + 8 * Ll;
#pragma unroll
        for (int nt = 0; nt < 8; nt++) {
            int lg = nt * 8 + qc;
            *(float2*)(r0 + lg) = make_float2(acc[mt][nt][0] + bv0, acc[mt][nt][1] + bv0);
            *(float2*)(r1 + lg) = make_float2(acc[mt][nt][2] + bv1, acc[mt][nt][3] + bv1);
        }
    }
}

// ---------------- launch ----------------------------------------------------
extern "C" void kernel_launch(void* const* d_in, const int* in_sizes, int n_in,
                              void* d_out, int out_size) {
    const float* u          = (const float*)d_in[0];
    const float* log_dt     = (const float*)d_in[1];
    const float* Lambda     = (const float*)d_in[2];
    const float* W          = (const float*)d_in[3];
    const float* D          = (const float*)d_in[4];
    const float* out_weight = (const float*)d_in[5];
    const float* out_bias   = (const float*)d_in[6];
    float* out = (float*)d_out;

    static int smem_set = 0;
    if (!smem_set) {
        cudaFuncSetAttribute(gemm_hmma, cudaFuncAttributeMaxDynamicSharedMemorySize, GEMM_SMEM);
        smem_set = 1;
    }

    prep_kernel<<<Hh, Nn>>>(log_dt, Lambda, W);
    owsplit_kernel<<<(Hh * Hh) / 256, 256>>>(out_weight);
    scan_kernel<<<Bb * (Hh / 8), 256>>>(u, D);
    dim3 grid(Ll / BN, Hh / BM, Bb);
    gemm_hmma<<<grid, 256, GEMM_SMEM>>>(out_bias, out);
}

// round 4
// speedup vs baseline: 1.7059x; 1.5536x over previous
#include <cuda_runtime.h>
#include <cuda_bf16.h>
#include <math.h>

#define Bb 16
#define Hh 512
#define Ll 2048
#define Nn 64
#define CH 64          // chunk length
#define NCH 32         // chunks per row

typedef unsigned long long ull;
typedef unsigned short u16;
typedef unsigned int u32;

// ---------------- scratch (device globals; no allocations allowed) ----------
__device__ float2 d_A [Hh * Nn];
__device__ float2 d_Wk[Hh * Nn];
// g in [b][h][l] layout, bf16 hi/lo
__device__ __align__(16) u16 d_gh[(size_t)Bb * Hh * Ll];
__device__ __align__(16) u16 d_gl[(size_t)Bb * Hh * Ll];
// out_weight bf16 hi/lo: [v][u]
__device__ __align__(16) u16 d_owh[Hh * Hh];
__device__ __align__(16) u16 d_owl[Hh * Hh];
// per-h chunk-scan matrices (hi/lo bf16)
__device__ __align__(16) u16 d_Ph[Hh * 128 * 64];  // P[m=128][j=64]
__device__ __align__(16) u16 d_Pl[Hh * 128 * 64];
__device__ __align__(16) u16 d_Mh[Hh * 64 * 128];  // M[t=64][m=128]
__device__ __align__(16) u16 d_Ml[Hh * 64 * 128];
__device__ __align__(16) u16 d_Th[Hh * 64 * 64];   // T[t=64][j=64]
__device__ __align__(16) u16 d_Tl[Hh * 64 * 64];
__device__ __align__(16) float2 d_A64[Hh * Nn];    // A^64

// ---------------- PTX helpers ----------------------------------------------
__device__ __forceinline__ u32 smem_u32(const void* p) {
    u32 a; asm("{ .reg .u64 t; cvta.to.shared.u64 t, %1; cvt.u32.u64 %0, t; }" : "=r"(a) : "l"(p));
    return a;
}
#define CP_ASYNC16(dst, src) asm volatile("cp.async.cg.shared.global [%0], [%1], 16;" :: "r"(dst), "l"(src) : "memory")
#define CP_COMMIT() asm volatile("cp.async.commit_group;" ::: "memory")
#define CP_WAIT(n)  asm volatile("cp.async.wait_group %0;" :: "n"(n) : "memory")

#define MMA16816(d, a, b) \
    asm volatile("mma.sync.aligned.m16n8k16.row.col.f32.bf16.bf16.f32 " \
        "{%0,%1,%2,%3}, {%4,%5,%6,%7}, {%8,%9}, {%0,%1,%2,%3};" \
        : "+f"((d)[0]), "+f"((d)[1]), "+f"((d)[2]), "+f"((d)[3]) \
        : "r"((a)[0]), "r"((a)[1]), "r"((a)[2]), "r"((a)[3]), "r"((b)[0]), "r"((b)[1]))

#define LDSM4T(r0, r1, r2, r3, addr) \
    asm volatile("ldmatrix.sync.aligned.m8n8.x4.trans.shared.b16 {%0,%1,%2,%3}, [%4];" \
        : "=r"(r0), "=r"(r1), "=r"(r2), "=r"(r3) : "r"(addr))

#define BARG(id) asm volatile("bar.sync %0, %1;" :: "r"(id), "r"(128) : "memory")

__device__ __forceinline__ void split_hl(float x, u16& h, u16& l) {
    __nv_bfloat16 bh = __float2bfloat16(x);
    h = __bfloat16_as_ushort(bh);
    l = __bfloat16_as_ushort(__float2bfloat16(x - __bfloat162float(bh)));
}

// ---------------- kernel 1a: DSS coefficient prep ---------------------------
__global__ void prep_kernel(const float* __restrict__ log_dt,
                            const float* __restrict__ Lambda,
                            const float* __restrict__ W) {
    int h = blockIdx.x;
    int n = threadIdx.x;
    float dt_re = expf(log_dt[2 * h + 0]);
    float dt_im = expf(log_dt[2 * h + 1]);
    float lr = Lambda[2 * n + 0], li = Lambda[2 * n + 1];
    float zr = dt_re * lr, zi = dt_im * li;
    float sgn = (lr > 0.f) ? -1.f : 1.f;
    float nr = zr * sgn, ni = zi * sgn;
    float er = expf(nr);
    float num_re = er * cosf(ni) - 1.f;
    float num_im = er * sinf(ni);
    float eL = expf(nr * (float)Ll);
    float den_re = eL * cosf(ni * (float)Ll) - 1.f;
    float den_im = eL * sinf(ni * (float)Ll);
    float xr = den_re * lr - den_im * li;
    float xi = den_re * li + den_im * lr;
    float inv = 1.f / (xr * xr + xi * xi + 1e-7f);
    float rr = xr * inv, ri = -xi * inv;
    float wr = W[(h * Nn + n) * 2 + 0], wi = W[(h * Nn + n) * 2 + 1];
    float t1r = wr * num_re - wi * num_im;
    float t1i = wr * num_im + wi * num_re;
    d_Wk[h * Nn + n] = make_float2(t1r * rr - t1i * ri, t1r * ri + t1i * rr);
    float ea = expf(zr);
    d_A [h * Nn + n] = make_float2(ea * cosf(zi), ea * sinf(zi));
}

// ---------------- kernel 1b: per-h chunk matrices ---------------------------
__global__ void prep2_kernel(const float* __restrict__ D) {
    int h = blockIdx.x;
    int n = threadIdx.x;   // 64
    __shared__ float part[2][64];
    __shared__ float kks[64];
    float2 A  = d_A [h * Nn + n];
    float2 Wc = d_Wk[h * Nn + n];
    float cr = 1.f, ci = 0.f;   // A^d
    for (int d = 0; d < 128; d++) {
        float wr = Wc.x * cr - Wc.y * ci;
        float wi = Wc.x * ci + Wc.y * cr;
        if (d < 64) {
            int j = 63 - d;
            split_hl(cr, d_Ph[(h * 128 + n) * 64 + j],      d_Pl[(h * 128 + n) * 64 + j]);
            split_hl(ci, d_Ph[(h * 128 + 64 + n) * 64 + j], d_Pl[(h * 128 + 64 + n) * 64 + j]);
            float s = wr;
            s += __shfl_xor_sync(0xffffffffu, s, 16);
            s += __shfl_xor_sync(0xffffffffu, s, 8);
            s += __shfl_xor_sync(0xffffffffu, s, 4);
            s += __shfl_xor_sync(0xffffffffu, s, 2);
            s += __shfl_xor_sync(0xffffffffu, s, 1);
            if ((n & 31) == 0) part[n >> 5][d] = s;
        }
        if (d >= 1 && d <= 64) {
            int t = d - 1;
            split_hl(wr,  d_Mh[(h * 64 + t) * 128 + n],      d_Ml[(h * 64 + t) * 128 + n]);
            split_hl(-wi, d_Mh[(h * 64 + t) * 128 + 64 + n], d_Ml[(h * 64 + t) * 128 + 64 + n]);
        }
        if (d == 64) d_A64[h * Nn + n] = make_float2(cr, ci);
        float ncr = A.x * cr - A.y * ci;
        ci = A.x * ci + A.y * cr;
        cr = ncr;
    }
    __syncthreads();
    kks[n] = part[0][n] + part[1][n];
    __syncthreads();
    float Dh = D[h];
    for (int t = 0; t < 64; t++) {
        float v = (n < t) ? kks[t - n] : ((n == t) ? (kks[0] + Dh) : 0.f);
        split_hl(v, d_Th[(h * 64 + t) * 64 + n], d_Tl[(h * 64 + t) * 64 + n]);
    }
}

// ---------------- kernel 1c: split out_weight -------------------------------
__global__ void owsplit_kernel(const float* __restrict__ ow) {
    int i = blockIdx.x * 256 + threadIdx.x;
    split_hl(ow[i], d_owh[i], d_owl[i]);
}

// ---------------- kernel 2: chunked tensor-core scan ------------------------
// CTA = h (512 CTAs, 256 threads = 2 groups of 4 warps; group g does b = 2*it+g).
// smem byte offsets:
#define OPh 0
#define OPl 18432
#define OMh 36864
#define OMl 54272
#define OTh 71680
#define OTl 80896
#define OA64 90112
#define OGRP 90624
#define GRPSZ 52224
#define GUh 0
#define GUl 4608
#define GCh 9216
#define GCl 17920
#define GBA 26624
#define GYs 43520
#define SCAN_SMEM (OGRP + 2 * GRPSZ)   // 195072

__global__ void __launch_bounds__(256, 1)
scan2_kernel(const float* __restrict__ u) {
    extern __shared__ __align__(16) char sm[];
    const u32 sb = smem_u32(sm);
    const int t = threadIdx.x;
    const int wid = t >> 5, lane = t & 31;
    const int g = wid >> 2, wg = wid & 3, gtid = t & 127;
    const int qr = lane >> 2, qc = (lane & 3) * 2;
    const int h = blockIdx.x;
    const int barid = 1 + g;

    // ---- load per-h matrices into smem (all 256 threads) -------------------
    for (int s = t; s < 1024; s += 256) {          // P: 128 rows x 8 segs
        int row = s >> 3, c = s & 7;
        u32 dst = (u32)(row * 144 + c * 16);
        size_t src = (size_t)(h * 128 + row) * 64 + c * 8;
        CP_ASYNC16(sb + OPh + dst, (const char*)(d_Ph + src));
        CP_ASYNC16(sb + OPl + dst, (const char*)(d_Pl + src));
    }
    for (int s = t; s < 1024; s += 256) {          // M: 64 rows x 16 segs
        int row = s >> 4, c = s & 15;
        u32 dst = (u32)(row * 272 + c * 16);
        size_t src = (size_t)(h * 64 + row) * 128 + c * 8;
        CP_ASYNC16(sb + OMh + dst, (const char*)(d_Mh + src));
        CP_ASYNC16(sb + OMl + dst, (const char*)(d_Ml + src));
    }
    for (int s = t; s < 512; s += 256) {           // T: 64 rows x 8 segs
        int row = s >> 3, c = s & 7;
        u32 dst = (u32)(row * 144 + c * 16);
        size_t src = (size_t)(h * 64 + row) * 64 + c * 8;
        CP_ASYNC16(sb + OTh + dst, (const char*)(d_Th + src));
        CP_ASYNC16(sb + OTl + dst, (const char*)(d_Tl + src));
    }
    if (t < 32) CP_ASYNC16(sb + OA64 + t * 16, (const char*)(d_A64 + h * Nn) + t * 16);
    CP_COMMIT(); CP_WAIT(0);
    __syncthreads();

    const u16* Ph = (const u16*)(sm + OPh);
    const u16* Pl = (const u16*)(sm + OPl);
    const u16* Mh = (const u16*)(sm + OMh);
    const u16* Ml = (const u16*)(sm + OMl);
    const u16* Th = (const u16*)(sm + OTh);
    const u16* Tl = (const u16*)(sm + OTl);
    const float2* A64s = (const float2*)(sm + OA64);
    char* gb = sm + OGRP + g * GRPSZ;
    u16*   Uh = (u16*)(gb + GUh);
    u16*   Ul = (u16*)(gb + GUl);
    u16*   Chs = (u16*)(gb + GCh);
    u16*   Cls = (u16*)(gb + GCl);
    float* BA = (float*)(gb + GBA);
    float* Ys = (float*)(gb + GYs);

    for (int it = 0; it < 8; it++) {
        int b = it * 2 + g;
        const float* up = u + ((size_t)b * Hh + h) * Ll;
        // ---- 1. convert u -> Uh/Ul (rows = chunk, 64 cols, stride 72) ------
        for (int i = gtid; i < 2048; i += 128) {
            float x = up[i];
            split_hl(x, Uh[(i >> 6) * 72 + (i & 63)], Ul[(i >> 6) * 72 + (i & 63)]);
        }
        BARG(barid);
        // ---- 2. GEMM1: BA[128 x 32] = P @ U --------------------------------
        {
            float acc[2][4][4];
#pragma unroll
            for (int mt = 0; mt < 2; mt++)
#pragma unroll
                for (int nt = 0; nt < 4; nt++)
#pragma unroll
                    for (int i = 0; i < 4; i++) acc[mt][nt][i] = 0.f;
#pragma unroll
            for (int kk = 0; kk < 64; kk += 16) {
                u32 ah[2][4], al[2][4];
#pragma unroll
                for (int mt = 0; mt < 2; mt++) {
                    int o = (wg * 32 + mt * 16 + qr) * 72 + kk + qc;
                    ah[mt][0] = *(const u32*)&Ph[o];
                    ah[mt][1] = *(const u32*)&Ph[o + 8 * 72];
                    ah[mt][2] = *(const u32*)&Ph[o + 8];
                    ah[mt][3] = *(const u32*)&Ph[o + 8 * 72 + 8];
                    al[mt][0] = *(const u32*)&Pl[o];
                    al[mt][1] = *(const u32*)&Pl[o + 8 * 72];
                    al[mt][2] = *(const u32*)&Pl[o + 8];
                    al[mt][3] = *(const u32*)&Pl[o + 8 * 72 + 8];
                }
                u32 uh[4][2], ul[4][2];
#pragma unroll
                for (int nt = 0; nt < 4; nt++) {
                    int o = (nt * 8 + qr) * 72 + kk + qc;
                    uh[nt][0] = *(const u32*)&Uh[o];
                    uh[nt][1] = *(const u32*)&Uh[o + 8];
                    ul[nt][0] = *(const u32*)&Ul[o];
                    ul[nt][1] = *(const u32*)&Ul[o + 8];
                }
#pragma unroll
                for (int mt = 0; mt < 2; mt++)
#pragma unroll
                    for (int nt = 0; nt < 4; nt++) {
                        MMA16816(acc[mt][nt], ah[mt], uh[nt]);
                        MMA16816(acc[mt][nt], ah[mt], ul[nt]);
                        MMA16816(acc[mt][nt], al[mt], uh[nt]);
                    }
            }
#pragma unroll
            for (int mt = 0; mt < 2; mt++)
#pragma unroll
                for (int nt = 0; nt < 4; nt++)
#pragma unroll
                    for (int i = 0; i < 4; i++) {
                        int m = wg * 32 + mt * 16 + qr + ((i >= 2) ? 8 : 0);
                        int ch = nt * 8 + qc + (i & 1);
                        BA[ch * 132 + m] = acc[mt][nt][i];
                    }
        }
        BARG(barid);
        // ---- 3. carry scan (64 threads) ------------------------------------
        if (gtid < 64) {
            int n = gtid;
            float2 a64 = A64s[n];
            float cr = 0.f, ci = 0.f;
            for (int ch = 0; ch < NCH; ch++) {
                split_hl(cr, Chs[ch * 136 + n],      Cls[ch * 136 + n]);
                split_hl(ci, Chs[ch * 136 + 64 + n], Cls[ch * 136 + 64 + n]);
                float br = BA[ch * 132 + n];
                float bi = BA[ch * 132 + 64 + n];
                float ncr = a64.x * cr - a64.y * ci + br;
                ci = a64.x * ci + a64.y * cr + bi;
                cr = ncr;
            }
        }
        BARG(barid);
        // ---- 4. GEMM2: Y[64 x 32] = T @ U + M @ C --------------------------
        {
            float acc[4][4];
#pragma unroll
            for (int nt = 0; nt < 4; nt++)
#pragma unroll
                for (int i = 0; i < 4; i++) acc[nt][i] = 0.f;
#pragma unroll
            for (int kk = 0; kk < 64; kk += 16) {
                u32 ah[4], al[4];
                int o = (wg * 16 + qr) * 72 + kk + qc;
                ah[0] = *(const u32*)&Th[o];
                ah[1] = *(const u32*)&Th[o + 8 * 72];
                ah[2] = *(const u32*)&Th[o + 8];
                ah[3] = *(const u32*)&Th[o + 8 * 72 + 8];
                al[0] = *(const u32*)&Tl[o];
                al[1] = *(const u32*)&Tl[o + 8 * 72];
                al[2] = *(const u32*)&Tl[o + 8];
                al[3] = *(const u32*)&Tl[o + 8 * 72 + 8];
#pragma unroll
                for (int nt = 0; nt < 4; nt++) {
                    int ob = (nt * 8 + qr) * 72 + kk + qc;
                    u32 bh[2] = { *(const u32*)&Uh[ob], *(const u32*)&Uh[ob + 8] };
                    u32 bl[2] = { *(const u32*)&Ul[ob], *(const u32*)&Ul[ob + 8] };
                    MMA16816(acc[nt], ah, bh);
                    MMA16816(acc[nt], ah, bl);
                    MMA16816(acc[nt], al, bh);
                }
            }
#pragma unroll
            for (int kk = 0; kk < 128; kk += 16) {
                u32 ah[4], al[4];
                int o = (wg * 16 + qr) * 136 + kk + qc;
                ah[0] = *(const u32*)&Mh[o];
                ah[1] = *(const u32*)&Mh[o + 8 * 136];
                ah[2] = *(const u32*)&Mh[o + 8];
                ah[3] = *(const u32*)&Mh[o + 8 * 136 + 8];
                al[0] = *(const u32*)&Ml[o];
                al[1] = *(const u32*)&Ml[o + 8 * 136];
                al[2] = *(const u32*)&Ml[o + 8];
                al[3] = *(const u32*)&Ml[o + 8 * 136 + 8];
#pragma unroll
                for (int nt = 0; nt < 4; nt++) {
                    int ob = (nt * 8 + qr) * 136 + kk + qc;
                    u32 bh[2] = { *(const u32*)&Chs[ob], *(const u32*)&Chs[ob + 8] };
                    u32 bl[2] = { *(const u32*)&Cls[ob], *(const u32*)&Cls[ob + 8] };
                    MMA16816(acc[nt], ah, bh);
                    MMA16816(acc[nt], ah, bl);
                    MMA16816(acc[nt], al, bh);
                }
            }
#pragma unroll
            for (int nt = 0; nt < 4; nt++)
#pragma unroll
                for (int i = 0; i < 4; i++) {
                    int tr = wg * 16 + qr + ((i >= 2) ? 8 : 0);
                    int ch = nt * 8 + qc + (i & 1);
                    Ys[ch * 68 + tr] = acc[nt][i];
                }
        }
        BARG(barid);
        // ---- 5. GELU + store g[b][h][l] hi/lo ------------------------------
        u16* gph = d_gh + ((size_t)b * Hh + h) * Ll;
        u16* gpl = d_gl + ((size_t)b * Hh + h) * Ll;
        for (int i = gtid; i < 2048; i += 128) {
            float y = Ys[(i >> 6) * 68 + (i & 63)];
            float gg = 0.5f * y * (1.f + erff(y * 0.70710678118654752f));
            u16 hi, lo;
            split_hl(gg, hi, lo);
            gph[i] = hi;
            gpl[i] = lo;
        }
        BARG(barid);
    }
}

// ---------------- kernel 3: HMMA split-bf16 GEMM (B via ldmatrix.trans) -----
#define BM 128
#define BN 128
#define BK 32
#define ASTR 40                     // u16 stride for A tiles
#define AMATB (BM * ASTR * 2)       // 10240 B
#define BSTR 136                    // u16 stride for B tiles (272 B rows)
#define BMATB (BK * BSTR * 2)       // 8704 B
#define STAGEB (2 * AMATB + 2 * BMATB)  // 37888
#define GEMM_SMEM (2 * STAGEB)          // 75776

__global__ void __launch_bounds__(256, 1)
gemm_hmma(const float* __restrict__ bias, float* __restrict__ out) {
    extern __shared__ __align__(16) char sm[];
    const u32 sb = smem_u32(sm);
    const int t = threadIdx.x;
    const int wid = t >> 5, lane = t & 31;
    const int warp_m = wid & 3, warp_n = wid >> 2;
    const int qr = lane >> 2, qc = (lane & 3) * 2;
    const int b  = blockIdx.z;
    const int v0 = blockIdx.y * BM;
    const int l0 = blockIdx.x * BN;
    // ldmatrix lane address components
    const int krow_l = (lane & 7) + ((lane >> 3) & 1) * 8;
    const int ncol_l = ((lane >> 4) & 1) * 8;

    float acc[2][8][4];
#pragma unroll
    for (int mt = 0; mt < 2; mt++)
#pragma unroll
        for (int nt = 0; nt < 8; nt++)
#pragma unroll
            for (int i = 0; i < 4; i++) acc[mt][nt][i] = 0.f;

    const int NK = Hh / BK;

    auto issue = [&](int c) {
        int k0 = c * BK;
        u32 st = sb + (c & 1) * STAGEB;
#pragma unroll
        for (int j = 0; j < 2; j++) {       // A: 512 segs
            int idx = t + 256 * j;
            int row = idx >> 2, seg = idx & 3;
            u32 so = (u32)(row * (ASTR * 2) + seg * 16);
            size_t ga = (size_t)(v0 + row) * Hh + k0 + seg * 8;
            CP_ASYNC16(st + so,         (const char*)(d_owh + ga));
            CP_ASYNC16(st + AMATB + so, (const char*)(d_owl + ga));
        }
#pragma unroll
        for (int j = 0; j < 2; j++) {       // B: 512 segs, rows = k (h)
            int idx = t + 256 * j;
            int row = idx >> 4, seg = idx & 15;
            u32 so = (u32)(row * (BSTR * 2) + seg * 16);
            size_t gg = ((size_t)b * Hh + k0 + row) * Ll + l0 + seg * 8;
            CP_ASYNC16(st + 2 * AMATB + so,         (const char*)(d_gh + gg));
            CP_ASYNC16(st + 2 * AMATB + BMATB + so, (const char*)(d_gl + gg));
        }
        CP_COMMIT();
    };

    issue(0);
    for (int c = 0; c < NK; c++) {
        if (c + 1 < NK) { issue(c + 1); CP_WAIT(1); }
        else            { CP_WAIT(0); }
        __syncthreads();

        const u16* AH = (const u16*)(sm + (c & 1) * STAGEB);
        const u16* AL = AH + AMATB / 2;
        u32 BHb = sb + (c & 1) * STAGEB + 2 * AMATB;
        u32 BLb = BHb + BMATB;

#pragma unroll
        for (int kk = 0; kk < BK; kk += 16) {
            u32 ah[2][4], al[2][4];
#pragma unroll
            for (int mt = 0; mt < 2; mt++) {
                int o = (warp_m * 32 + mt * 16 + qr) * ASTR + kk + qc;
                ah[mt][0] = *(const u32*)&AH[o];
                ah[mt][1] = *(const u32*)&AH[o + 8 * ASTR];
                ah[mt][2] = *(const u32*)&AH[o + 8];
                ah[mt][3] = *(const u32*)&AH[o + 8 * ASTR + 8];
                al[mt][0] = *(const u32*)&AL[o];
                al[mt][1] = *(const u32*)&AL[o + 8 * ASTR];
                al[mt][2] = *(const u32*)&AL[o + 8];
                al[mt][3] = *(const u32*)&AL[o + 8 * ASTR + 8];
            }
            u32 bh[8][2], bl[8][2];
#pragma unroll
            for (int p = 0; p < 4; p++) {
                u32 off = (u32)((kk + krow_l) * (BSTR * 2) +
                                (warp_n * 64 + p * 16 + ncol_l) * 2);
                LDSM4T(bh[2 * p][0], bh[2 * p][1], bh[2 * p + 1][0], bh[2 * p + 1][1], BHb + off);
                LDSM4T(bl[2 * p][0], bl[2 * p][1], bl[2 * p + 1][0], bl[2 * p + 1][1], BLb + off);
            }
#pragma unroll
            for (int mt = 0; mt < 2; mt++)
#pragma unroll
                for (int nt = 0; nt < 8; nt++) {
                    MMA16816(acc[mt][nt], ah[mt], bh[nt]);
                    MMA16816(acc[mt][nt], ah[mt], bl[nt]);
                    MMA16816(acc[mt][nt], al[mt], bh[nt]);
                }
        }
        __syncthreads();
    }

#pragma unroll
    for (int mt = 0; mt < 2; mt++) {
        int vg = v0 + warp_m * 32 + mt * 16 + qr;
        float bv0 = bias[vg];
        float bv1 = bias[vg + 8];
        float* r0 = out + (size_t)(b * Hh + vg) * Ll + l0 + warp_n * 64;
        float* r1 = r0 + 8 * Ll;
#pragma unroll
        for (int nt = 0; nt < 8; nt++) {
            int lg = nt * 8 + qc;
            *(float2*)(r0 + lg) = make_float2(acc[mt][nt][0] + bv0, acc[mt][nt][1] + bv0);
            *(float2*)(r1 + lg) = make_float2(acc[mt][nt][2] + bv1, acc[mt][nt][3] + bv1);
        }
    }
}

// ---------------- launch ----------------------------------------------------
extern "C" void kernel_launch(void* const* d_in, const int* in_sizes, int n_in,
                              void* d_out, int out_size) {
    const float* u          = (const float*)d_in[0];
    const float* log_dt     = (const float*)d_in[1];
    const float* Lambda     = (const float*)d_in[2];
    const float* W          = (const float*)d_in[3];
    const float* D          = (const float*)d_in[4];
    const float* out_weight = (const float*)d_in[5];
    const float* out_bias   = (const float*)d_in[6];
    float* out = (float*)d_out;

    cudaFuncSetAttribute(scan2_kernel, cudaFuncAttributeMaxDynamicSharedMemorySize, SCAN_SMEM);
    cudaFuncSetAttribute(gemm_hmma,   cudaFuncAttributeMaxDynamicSharedMemorySize, GEMM_SMEM);

    prep_kernel<<<Hh, Nn>>>(log_dt, Lambda, W);
    prep2_kernel<<<Hh, Nn>>>(D);
    owsplit_kernel<<<(Hh * Hh) / 256, 256>>>(out_weight);
    scan2_kernel<<<Hh, 256, SCAN_SMEM>>>(u);
    dim3 grid(Ll / BN, Hh / BM, Bb);
    gemm_hmma<<<grid, 256, GEMM_SMEM>>>(out_bias, out);
}

// round 5
// speedup vs baseline: 3.5774x; 2.0970x over previous
#include <cuda_runtime.h>
#include <cuda_fp16.h>
#include <math.h>

#define Bb 16
#define Hh 512
#define Ll 2048
#define Nn 64
#define CH 64
#define NCH 32

typedef unsigned long long ull;
typedef unsigned short u16;
typedef unsigned int u32;

// ---------------- scratch (device globals; no allocations allowed) ----------
__device__ float2 d_A [Hh * Nn];
__device__ float2 d_Wk[Hh * Nn];
// g in [b][h][l] layout, fp16
__device__ __align__(16) u16 d_g[(size_t)Bb * Hh * Ll];
// out_weight fp16: [v][u]
__device__ __align__(16) u16 d_ow[Hh * Hh];
// per-h chunk-scan matrices (fp16)
__device__ __align__(16) u16 d_P[Hh * 128 * 64];  // P[m=128][j=64]
__device__ __align__(16) u16 d_M[Hh * 64 * 128];  // M[t=64][m=128]
__device__ __align__(16) u16 d_T[Hh * 64 * 64];   // T[t=64][j=64]
__device__ __align__(16) float2 d_A64[Hh * Nn];   // A^64

// ---------------- PTX helpers ----------------------------------------------
__device__ __forceinline__ u32 smem_u32(const void* p) {
    u32 a; asm("{ .reg .u64 t; cvta.to.shared.u64 t, %1; cvt.u32.u64 %0, t; }" : "=r"(a) : "l"(p));
    return a;
}
#define CP_ASYNC16(dst, src) asm volatile("cp.async.cg.shared.global [%0], [%1], 16;" :: "r"(dst), "l"(src) : "memory")
#define CP_COMMIT() asm volatile("cp.async.commit_group;" ::: "memory")
#define CP_WAIT(n)  asm volatile("cp.async.wait_group %0;" :: "n"(n) : "memory")

#define MMAF16(d, a, b) \
    asm volatile("mma.sync.aligned.m16n8k16.row.col.f32.f16.f16.f32 " \
        "{%0,%1,%2,%3}, {%4,%5,%6,%7}, {%8,%9}, {%0,%1,%2,%3};" \
        : "+f"((d)[0]), "+f"((d)[1]), "+f"((d)[2]), "+f"((d)[3]) \
        : "r"((a)[0]), "r"((a)[1]), "r"((a)[2]), "r"((a)[3]), "r"((b)[0]), "r"((b)[1]))

#define LDSM4T(r0, r1, r2, r3, addr) \
    asm volatile("ldmatrix.sync.aligned.m8n8.x4.trans.shared.b16 {%0,%1,%2,%3}, [%4];" \
        : "=r"(r0), "=r"(r1), "=r"(r2), "=r"(r3) : "r"(addr))

#define BARG(id) asm volatile("bar.sync %0, %1;" :: "r"(id), "r"(128) : "memory")

__device__ __forceinline__ u16 f2h(float x) {
    return __half_as_ushort(__float2half_rn(x));
}

// ---------------- kernel 1a: DSS coefficient prep ---------------------------
__global__ void prep_kernel(const float* __restrict__ log_dt,
                            const float* __restrict__ Lambda,
                            const float* __restrict__ W) {
    int h = blockIdx.x;
    int n = threadIdx.x;
    float dt_re = expf(log_dt[2 * h + 0]);
    float dt_im = expf(log_dt[2 * h + 1]);
    float lr = Lambda[2 * n + 0], li = Lambda[2 * n + 1];
    float zr = dt_re * lr, zi = dt_im * li;
    float sgn = (lr > 0.f) ? -1.f : 1.f;
    float nr = zr * sgn, ni = zi * sgn;
    float er = expf(nr);
    float num_re = er * cosf(ni) - 1.f;
    float num_im = er * sinf(ni);
    float eL = expf(nr * (float)Ll);
    float den_re = eL * cosf(ni * (float)Ll) - 1.f;
    float den_im = eL * sinf(ni * (float)Ll);
    float xr = den_re * lr - den_im * li;
    float xi = den_re * li + den_im * lr;
    float inv = 1.f / (xr * xr + xi * xi + 1e-7f);
    float rr = xr * inv, ri = -xi * inv;
    float wr = W[(h * Nn + n) * 2 + 0], wi = W[(h * Nn + n) * 2 + 1];
    float t1r = wr * num_re - wi * num_im;
    float t1i = wr * num_im + wi * num_re;
    d_Wk[h * Nn + n] = make_float2(t1r * rr - t1i * ri, t1r * ri + t1i * rr);
    float ea = expf(zr);
    d_A [h * Nn + n] = make_float2(ea * cosf(zi), ea * sinf(zi));
}

// ---------------- kernel 1b: per-h chunk matrices (fp16) --------------------
__global__ void prep2_kernel(const float* __restrict__ D) {
    int h = blockIdx.x;
    int n = threadIdx.x;   // 64
    __shared__ float part[2][64];
    __shared__ float kks[64];
    float2 A  = d_A [h * Nn + n];
    float2 Wc = d_Wk[h * Nn + n];
    float cr = 1.f, ci = 0.f;   // A^d
    for (int d = 0; d < 128; d++) {
        float wr = Wc.x * cr - Wc.y * ci;
        float wi = Wc.x * ci + Wc.y * cr;
        if (d < 64) {
            int j = 63 - d;
            d_P[(h * 128 + n) * 64 + j]      = f2h(cr);
            d_P[(h * 128 + 64 + n) * 64 + j] = f2h(ci);
            float s = wr;
            s += __shfl_xor_sync(0xffffffffu, s, 16);
            s += __shfl_xor_sync(0xffffffffu, s, 8);
            s += __shfl_xor_sync(0xffffffffu, s, 4);
            s += __shfl_xor_sync(0xffffffffu, s, 2);
            s += __shfl_xor_sync(0xffffffffu, s, 1);
            if ((n & 31) == 0) part[n >> 5][d] = s;
        }
        if (d >= 1 && d <= 64) {
            int t = d - 1;
            d_M[(h * 64 + t) * 128 + n]      = f2h(wr);
            d_M[(h * 64 + t) * 128 + 64 + n] = f2h(-wi);
        }
        if (d == 64) d_A64[h * Nn + n] = make_float2(cr, ci);
        float ncr = A.x * cr - A.y * ci;
        ci = A.x * ci + A.y * cr;
        cr = ncr;
    }
    __syncthreads();
    kks[n] = part[0][n] + part[1][n];
    __syncthreads();
    float Dh = D[h];
    for (int t = 0; t < 64; t++) {
        float v = (n < t) ? kks[t - n] : ((n == t) ? (kks[0] + Dh) : 0.f);
        d_T[(h * 64 + t) * 64 + n] = f2h(v);
    }
}

// ---------------- kernel 1c: out_weight -> fp16 -----------------------------
__global__ void owhalf_kernel(const float* __restrict__ ow) {
    int i = blockIdx.x * 256 + threadIdx.x;
    d_ow[i] = f2h(ow[i]);
}

// ---------------- kernel 2: chunked tensor-core scan (fp16, 4 groups) -------
#define OP 0
#define OM 18432
#define OT 35840
#define OA64 45056
#define OGRP 45568
#define GU 0
#define GC 4608
#define GBA 13312
#define GY 30208
#define GRPSZ 38912
#define SCAN_SMEM (OGRP + 4 * GRPSZ)   // 201216

__global__ void __launch_bounds__(512, 1)
scan2_kernel(const float* __restrict__ u) {
    extern __shared__ __align__(16) char sm[];
    const u32 sb = smem_u32(sm);
    const int t = threadIdx.x;
    const int wid = t >> 5, lane = t & 31;
    const int g = wid >> 2, wg = wid & 3, gtid = t & 127;
    const int qr = lane >> 2, qc = (lane & 3) * 2;
    const int h = blockIdx.x;
    const int barid = 1 + g;

    // ---- load per-h matrices into smem (all 512 threads) -------------------
    for (int s = t; s < 1024; s += 512) {          // P: 128 rows x 8 segs
        int row = s >> 3, c = s & 7;
        CP_ASYNC16(sb + OP + (u32)(row * 144 + c * 16),
                   (const char*)(d_P + (size_t)(h * 128 + row) * 64 + c * 8));
    }
    for (int s = t; s < 1024; s += 512) {          // M: 64 rows x 16 segs
        int row = s >> 4, c = s & 15;
        CP_ASYNC16(sb + OM + (u32)(row * 272 + c * 16),
                   (const char*)(d_M + (size_t)(h * 64 + row) * 128 + c * 8));
    }
    for (int s = t; s < 512; s += 512) {           // T: 64 rows x 8 segs
        int row = s >> 3, c = s & 7;
        CP_ASYNC16(sb + OT + (u32)(row * 144 + c * 16),
                   (const char*)(d_T + (size_t)(h * 64 + row) * 64 + c * 8));
    }
    if (t < 32) CP_ASYNC16(sb + OA64 + t * 16, (const char*)(d_A64 + h * Nn) + t * 16);
    CP_COMMIT(); CP_WAIT(0);
    __syncthreads();

    const u16* Ps = (const u16*)(sm + OP);
    const u16* Ms = (const u16*)(sm + OM);
    const u16* Ts = (const u16*)(sm + OT);
    const float2* A64s = (const float2*)(sm + OA64);
    char* gb = sm + OGRP + g * GRPSZ;
    u16*   Us  = (u16*)(gb + GU);
    u16*   Cs  = (u16*)(gb + GC);
    float* BA  = (float*)(gb + GBA);
    float* Ys  = (float*)(gb + GY);

    for (int it = 0; it < 4; it++) {
        int b = it * 4 + g;
        const float* up = u + ((size_t)b * Hh + h) * Ll;
        // ---- 1. convert u -> fp16 (rows = chunk, 64 cols, stride 72) -------
        for (int i = gtid; i < 2048; i += 128)
            Us[(i >> 6) * 72 + (i & 63)] = f2h(up[i]);
        BARG(barid);
        // ---- 2. GEMM1: BA[128 x 32] = P @ U --------------------------------
        {
            float acc[2][4][4];
#pragma unroll
            for (int mt = 0; mt < 2; mt++)
#pragma unroll
                for (int nt = 0; nt < 4; nt++)
#pragma unroll
                    for (int i = 0; i < 4; i++) acc[mt][nt][i] = 0.f;
#pragma unroll
            for (int kk = 0; kk < 64; kk += 16) {
                u32 ah[2][4];
#pragma unroll
                for (int mt = 0; mt < 2; mt++) {
                    int o = (wg * 32 + mt * 16 + qr) * 72 + kk + qc;
                    ah[mt][0] = *(const u32*)&Ps[o];
                    ah[mt][1] = *(const u32*)&Ps[o + 8 * 72];
                    ah[mt][2] = *(const u32*)&Ps[o + 8];
                    ah[mt][3] = *(const u32*)&Ps[o + 8 * 72 + 8];
                }
                u32 uh[4][2];
#pragma unroll
                for (int nt = 0; nt < 4; nt++) {
                    int o = (nt * 8 + qr) * 72 + kk + qc;
                    uh[nt][0] = *(const u32*)&Us[o];
                    uh[nt][1] = *(const u32*)&Us[o + 8];
                }
#pragma unroll
                for (int mt = 0; mt < 2; mt++)
#pragma unroll
                    for (int nt = 0; nt < 4; nt++)
                        MMAF16(acc[mt][nt], ah[mt], uh[nt]);
            }
#pragma unroll
            for (int mt = 0; mt < 2; mt++)
#pragma unroll
                for (int nt = 0; nt < 4; nt++)
#pragma unroll
                    for (int i = 0; i < 4; i++) {
                        int m = wg * 32 + mt * 16 + qr + ((i >= 2) ? 8 : 0);
                        int ch = nt * 8 + qc + (i & 1);
                        BA[ch * 132 + m] = acc[mt][nt][i];
                    }
        }
        BARG(barid);
        // ---- 3. carry scan (64 threads/group) ------------------------------
        if (gtid < 64) {
            int n = gtid;
            float2 a64 = A64s[n];
            float cr = 0.f, ci = 0.f;
            for (int ch = 0; ch < NCH; ch++) {
                Cs[ch * 136 + n]      = f2h(cr);
                Cs[ch * 136 + 64 + n] = f2h(ci);
                float br = BA[ch * 132 + n];
                float bi = BA[ch * 132 + 64 + n];
                float ncr = a64.x * cr - a64.y * ci + br;
                ci = a64.x * ci + a64.y * cr + bi;
                cr = ncr;
            }
        }
        BARG(barid);
        // ---- 4. GEMM2: Y[64 x 32] = T @ U + M @ C --------------------------
        {
            float acc[4][4];
#pragma unroll
            for (int nt = 0; nt < 4; nt++)
#pragma unroll
                for (int i = 0; i < 4; i++) acc[nt][i] = 0.f;
#pragma unroll
            for (int kk = 0; kk < 64; kk += 16) {
                u32 ah[4];
                int o = (wg * 16 + qr) * 72 + kk + qc;
                ah[0] = *(const u32*)&Ts[o];
                ah[1] = *(const u32*)&Ts[o + 8 * 72];
                ah[2] = *(const u32*)&Ts[o + 8];
                ah[3] = *(const u32*)&Ts[o + 8 * 72 + 8];
#pragma unroll
                for (int nt = 0; nt < 4; nt++) {
                    int ob = (nt * 8 + qr) * 72 + kk + qc;
                    u32 bh[2] = { *(const u32*)&Us[ob], *(const u32*)&Us[ob + 8] };
                    MMAF16(acc[nt], ah, bh);
                }
            }
#pragma unroll
            for (int kk = 0; kk < 128; kk += 16) {
                u32 ah[4];
                int o = (wg * 16 + qr) * 136 + kk + qc;
                ah[0] = *(const u32*)&Ms[o];
                ah[1] = *(const u32*)&Ms[o + 8 * 136];
                ah[2] = *(const u32*)&Ms[o + 8];
                ah[3] = *(const u32*)&Ms[o + 8 * 136 + 8];
#pragma unroll
                for (int nt = 0; nt < 4; nt++) {
                    int ob = (nt * 8 + qr) * 136 + kk + qc;
                    u32 bh[2] = { *(const u32*)&Cs[ob], *(const u32*)&Cs[ob + 8] };
                    MMAF16(acc[nt], ah, bh);
                }
            }
#pragma unroll
            for (int nt = 0; nt < 4; nt++)
#pragma unroll
                for (int i = 0; i < 4; i++) {
                    int tr = wg * 16 + qr + ((i >= 2) ? 8 : 0);
                    int ch = nt * 8 + qc + (i & 1);
                    Ys[ch * 68 + tr] = acc[nt][i];
                }
        }
        BARG(barid);
        // ---- 5. GELU + store g[b][h][l] fp16 -------------------------------
        u16* gp = d_g + ((size_t)b * Hh + h) * Ll;
        for (int i = gtid; i < 2048; i += 128) {
            float y = Ys[(i >> 6) * 68 + (i & 63)];
            float gg = 0.5f * y * (1.f + erff(y * 0.70710678118654752f));
            gp[i] = f2h(gg);
        }
        BARG(barid);
    }
}

// ---------------- kernel 3: HMMA fp16 GEMM (B via ldmatrix.trans) -----------
#define BM 128
#define BN 128
#define BK 32
#define ASTR 40                     // u16 stride for A tiles (80 B rows)
#define AMATB (BM * ASTR * 2)       // 10240 B
#define BSTR 136                    // u16 stride for B tiles (272 B rows)
#define BMATB (BK * BSTR * 2)       // 8704 B
#define STAGEB (AMATB + BMATB)      // 18944
#define GEMM_SMEM (2 * STAGEB)      // 37888

__global__ void __launch_bounds__(256, 2)
gemm_hmma(const float* __restrict__ bias, float* __restrict__ out) {
    extern __shared__ __align__(16) char sm[];
    const u32 sb = smem_u32(sm);
    const int t = threadIdx.x;
    const int wid = t >> 5, lane = t & 31;
    const int warp_m = wid & 3, warp_n = wid >> 2;
    const int qr = lane >> 2, qc = (lane & 3) * 2;
    const int b  = blockIdx.z;
    const int v0 = blockIdx.y * BM;
    const int l0 = blockIdx.x * BN;
    const int krow_l = (lane & 7) + ((lane >> 3) & 1) * 8;
    const int ncol_l = ((lane >> 4) & 1) * 8;

    float acc[2][8][4];
#pragma unroll
    for (int mt = 0; mt < 2; mt++)
#pragma unroll
        for (int nt = 0; nt < 8; nt++)
#pragma unroll
            for (int i = 0; i < 4; i++) acc[mt][nt][i] = 0.f;

    const int NK = Hh / BK;

    auto issue = [&](int c) {
        int k0 = c * BK;
        u32 st = sb + (c & 1) * STAGEB;
#pragma unroll
        for (int j = 0; j < 2; j++) {       // A: 512 segs (128 rows x 4)
            int idx = t + 256 * j;
            int row = idx >> 2, seg = idx & 3;
            CP_ASYNC16(st + (u32)(row * (ASTR * 2) + seg * 16),
                       (const char*)(d_ow + (size_t)(v0 + row) * Hh + k0 + seg * 8));
        }
#pragma unroll
        for (int j = 0; j < 2; j++) {       // B: 512 segs (32 rows x 16)
            int idx = t + 256 * j;
            int row = idx >> 4, seg = idx & 15;
            CP_ASYNC16(st + AMATB + (u32)(row * (BSTR * 2) + seg * 16),
                       (const char*)(d_g + ((size_t)b * Hh + k0 + row) * Ll + l0 + seg * 8));
        }
        CP_COMMIT();
    };

    issue(0);
    for (int c = 0; c < NK; c++) {
        if (c + 1 < NK) { issue(c + 1); CP_WAIT(1); }
        else            { CP_WAIT(0); }
        __syncthreads();

        const u16* AH = (const u16*)(sm + (c & 1) * STAGEB);
        u32 BHb = sb + (c & 1) * STAGEB + AMATB;

#pragma unroll
        for (int kk = 0; kk < BK; kk += 16) {
            u32 ah[2][4];
#pragma unroll
            for (int mt = 0; mt < 2; mt++) {
                int o = (warp_m * 32 + mt * 16 + qr) * ASTR + kk + qc;
                ah[mt][0] = *(const u32*)&AH[o];
                ah[mt][1] = *(const u32*)&AH[o + 8 * ASTR];
                ah[mt][2] = *(const u32*)&AH[o + 8];
                ah[mt][3] = *(const u32*)&AH[o + 8 * ASTR + 8];
            }
            u32 bh[8][2];
#pragma unroll
            for (int p = 0; p < 4; p++) {
                u32 off = (u32)((kk + krow_l) * (BSTR * 2) +
                                (warp_n * 64 + p * 16 + ncol_l) * 2);
                LDSM4T(bh[2 * p][0], bh[2 * p][1], bh[2 * p + 1][0], bh[2 * p + 1][1], BHb + off);
            }
#pragma unroll
            for (int mt = 0; mt < 2; mt++)
#pragma unroll
                for (int nt = 0; nt < 8; nt++)
                    MMAF16(acc[mt][nt], ah[mt], bh[nt]);
        }
        __syncthreads();
    }

#pragma unroll
    for (int mt = 0; mt < 2; mt++) {
        int vg = v0 + warp_m * 32 + mt * 16 + qr;
        float bv0 = bias[vg];
        float bv1 = bias[vg + 8];
        float* r0 = out + (size_t)(b * Hh + vg) * Ll + l0 + warp_n * 64;
        float* r1 = r0 + 8 * Ll;
#pragma unroll
        for (int nt = 0; nt < 8; nt++) {
            int lg = nt * 8 + qc;
            *(float2*)(r0 + lg) = make_float2(acc[mt][nt][0] + bv0, acc[mt][nt][1] + bv0);
            *(float2*)(r1 + lg) = make_float2(acc[mt][nt][2] + bv1, acc[mt][nt][3] + bv1);
        }
    }
}

// ---------------- launch ----------------------------------------------------
extern "C" void kernel_launch(void* const* d_in, const int* in_sizes, int n_in,
                              void* d_out, int out_size) {
    const float* u          = (const float*)d_in[0];
    const float* log_dt     = (const float*)d_in[1];
    const float* Lambda     = (const float*)d_in[2];
    const float* W          = (const float*)d_in[3];
    const float* D          = (const float*)d_in[4];
    const float* out_weight = (const float*)d_in[5];
    const float* out_bias   = (const float*)d_in[6];
    float* out = (float*)d_out;

    cudaFuncSetAttribute(scan2_kernel, cudaFuncAttributeMaxDynamicSharedMemorySize, SCAN_SMEM);
    cudaFuncSetAttribute(gemm_hmma,   cudaFuncAttributeMaxDynamicSharedMemorySize, GEMM_SMEM);

    prep_kernel<<<Hh, Nn>>>(log_dt, Lambda, W);
    prep2_kernel<<<Hh, Nn>>>(D);
    owhalf_kernel<<<(Hh * Hh) / 256, 256>>>(out_weight);
    scan2_kernel<<<Hh, 512, SCAN_SMEM>>>(u);
    dim3 grid(Ll / BN, Hh / BM, Bb);
    gemm_hmma<<<grid, 256, GEMM_SMEM>>>(out_bias, out);
}